// round 10
// baseline (speedup 1.0000x reference)
#include <cuda_runtime.h>
#include <math.h>

#define SS 512
#define BB 128
#define HH 1024
#define G4 4096
#define NBLK 128

// ---------------- static device scratch (no runtime allocation) ------------------
__device__ float g_Wcat[(size_t)G4 * HH];   // interleaved combined weights (t>=1)
__device__ float g_W0cat[(size_t)G4 * HH];  // interleaved step-0 weights (x=0)
__device__ float g_bc[G4];                  // interleaved combined biases
__device__ float g_h0[BB * HH];             // initial hidden state
__device__ float g_hist[(size_t)BB * SS * HH]; // h_t history [b][t][h]
__device__ float g_ec[BB * SS * 2];         // enc projected through Wp ctx rows [b][s][2]
__device__ unsigned g_arr;                  // grid-barrier arrive counter
__device__ unsigned g_rel;                  // grid-barrier release generation

// ---------------- f32x2 packed helpers -------------------------------------------
__device__ __forceinline__ unsigned long long pk2(float x) {
    unsigned long long r;
    asm("mov.b64 %0, {%1, %1};" : "=l"(r) : "f"(x));
    return r;
}
__device__ __forceinline__ void fma2(unsigned long long& d,
                                     unsigned long long a, unsigned long long b) {
    asm("fma.rn.f32x2 %0, %1, %2, %0;" : "+l"(d) : "l"(a), "l"(b));
}
__device__ __forceinline__ void unp(unsigned long long v, float& a, float& b) {
    asm("mov.b64 {%0, %1}, %2;" : "=f"(a), "=f"(b) : "l"(v));
}

// ---------------- prep: interleaved weights/biases, h0, barrier reset ------------
// interleaved col n = u*4 + g, gate g in {0:r, 1:z, 2:xn, 3:hn}
__global__ void prep_kernel(const float* __restrict__ Wih, const float* __restrict__ Whh,
                            const float* __restrict__ bih, const float* __restrict__ bhh,
                            const float* __restrict__ last) {
    const size_t total = (size_t)G4 * HH;
    const size_t tid0 = (size_t)blockIdx.x * blockDim.x + threadIdx.x;
    if (tid0 == 0) { g_arr = 0u; g_rel = 0u; }
    for (size_t idx = tid0; idx < total; idx += (size_t)gridDim.x * blockDim.x) {
        const int n = (int)(idx >> 10), k = (int)(idx & 1023);
        const int u = n >> 2, g = n & 3;
        float wc, w0;
        if (g == 0)      { float a = Wih[(size_t)u * HH + k],            b = Whh[(size_t)u * HH + k];            wc = a + b; w0 = b; }
        else if (g == 1) { float a = Wih[(size_t)(HH + u) * HH + k],     b = Whh[(size_t)(HH + u) * HH + k];     wc = a + b; w0 = b; }
        else if (g == 2) { wc = Wih[(size_t)(2 * HH + u) * HH + k];      w0 = 0.f; }
        else             { float b = Whh[(size_t)(2 * HH + u) * HH + k]; wc = b;    w0 = b; }
        g_Wcat[idx] = wc;
        g_W0cat[idx] = w0;
        if (k == 0) {
            float bc;
            if (g == 0)      bc = bih[u] + bhh[u];
            else if (g == 1) bc = bih[HH + u] + bhh[HH + u];
            else if (g == 2) bc = bih[2 * HH + u];
            else             bc = bhh[2 * HH + u];
            g_bc[n] = bc;
        }
        if (idx < (size_t)BB * HH) g_h0[idx] = last[idx];
    }
}

// ---------------- ec: g_ec[b][s][j] = Wp[j,:1024] . enc[s][b][:] -----------------
__global__ void __launch_bounds__(256) ec_kernel(const float* __restrict__ enc,
                                                 const float* __restrict__ Wp) {
    const int gw = (blockIdx.x * 256 + threadIdx.x) >> 5;   // 0..2047
    const int l = threadIdx.x & 31;
    for (int rr = 0; rr < 32; rr++) {
        const int row = gw * 32 + rr;                        // = s*BB + b
        const int s = row >> 7, b = row & 127;
        const float* e = enc + (size_t)row * HH;
        float p0 = 0.f, p1 = 0.f;
#pragma unroll
        for (int c = 0; c < 8; c++) {
            float4 v  = *(const float4*)(e + l * 4 + c * 128);
            float4 w0 = *(const float4*)(Wp + l * 4 + c * 128);
            float4 w1 = *(const float4*)(Wp + 2048 + l * 4 + c * 128);
            p0 += v.x * w0.x + v.y * w0.y + v.z * w0.z + v.w * w0.w;
            p1 += v.x * w1.x + v.y * w1.y + v.z * w1.z + v.w * w1.w;
        }
#pragma unroll
        for (int o = 16; o; o >>= 1) {
            p0 += __shfl_xor_sync(~0u, p0, o);
            p1 += __shfl_xor_sync(~0u, p1, o);
        }
        if (l == 0) {
            g_ec[((size_t)b * SS + s) * 2 + 0] = p0;
            g_ec[((size_t)b * SS + s) * 2 + 1] = p1;
        }
    }
}

// ---------------- persistent recurrence: 512 steps, 1 grid barrier each ----------
// 128 blocks = 2 m-tiles (batch 64) x 64 n-tiles (64 interleaved gate cols = 16 units).
// 256 threads (2 warps/SMSP for latency hiding), thread tile 8m x 2n (one unit's
// gate pair per lane; gates completed via shfl.xor(1) in the epilogue).
// Conflict-free STS loader layout; double-buffered smem + register prefetch.
__global__ void __launch_bounds__(256, 1) rec_kernel() {
    __shared__ float As[2][16][68];    // [buf][k][m], pitch 68: 16B-aligned rows
    __shared__ float Bs[2][16][68];    // [buf][k][n]
    const int tid = threadIdx.x;
    const int blk = blockIdx.x;
    const int m0 = (blk >> 6) * 64;    // 2 m-tiles
    const int n0 = (blk & 63) * 64;    // 64 n-tiles
    const int tm = tid >> 5;           // warp 0..7 -> rows tm*8..+7
    const int tn = tid & 31;           // col pair 2*tn (within 64-col tile)
    // loader: warp w covers rows (w&3)*16 + r4, k-offset (w>>2)*8 + (tid&1)*4
    // => per-STS banks {row, row+16}: conflict-free
    const int r4 = (tid >> 1) & 15;
    const int ldrow = ((tid >> 5) & 3) * 16 + r4;          // 0..63
    const int ldko  = ((tid >> 7) << 3) + ((tid & 1) << 2); // 0,4,8,12
    const int u = (n0 >> 2) + (tn >> 1);   // hidden unit of this lane pair
    const int par = tn & 1;                // 0: holds (r,z); 1: holds (xn,hn)
    unsigned gen = 0;

#define STORE_A(buf, v)                                        \
    { As[buf][ldko + 0][ldrow] = (v).x; As[buf][ldko + 1][ldrow] = (v).y; \
      As[buf][ldko + 2][ldrow] = (v).z; As[buf][ldko + 3][ldrow] = (v).w; }
#define STORE_B(buf, v)                                        \
    { Bs[buf][ldko + 0][ldrow] = (v).x; Bs[buf][ldko + 1][ldrow] = (v).y; \
      Bs[buf][ldko + 2][ldrow] = (v).z; Bs[buf][ldko + 3][ldrow] = (v).w; }

    for (int t = 0; t < SS; t++) {
        const float* W = (t == 0) ? g_W0cat : g_Wcat;
        const float* arow = ((t == 0) ? (g_h0 + (size_t)(m0 + ldrow) * HH)
                                      : (g_hist + ((size_t)(m0 + ldrow) * SS + (t - 1)) * HH)) + ldko;
        const float* brow = W + (size_t)(n0 + ldrow) * HH + ldko;

        // prefetch h_prev for epilogue (4 batches this lane finalizes)
        float hp[4];
#pragma unroll
        for (int i = 0; i < 4; i++) {
            const int b = m0 + tm * 8 + par * 4 + i;
            hp[i] = (t == 0) ? g_h0[(size_t)b * HH + u]
                             : g_hist[((size_t)b * SS + (t - 1)) * HH + u];
        }

        // prologue: chunk 0 -> buf0, chunk 1 -> regs
        float4 aR = *(const float4*)arow;
        float4 bR = *(const float4*)brow;
        STORE_A(0, aR);
        STORE_B(0, bR);
        aR = *(const float4*)(arow + 16);
        bR = *(const float4*)(brow + 16);
        __syncthreads();

        unsigned long long acc[8];
#pragma unroll
        for (int i = 0; i < 8; i++) acc[i] = 0ull;

        for (int c = 0; c < 64; c++) {
            const int cur = c & 1;
            if (c < 63) { STORE_A(cur ^ 1, aR); STORE_B(cur ^ 1, bR); }
            if (c < 62) {
                const int off = (c + 2) * 16;
                aR = *(const float4*)(arow + off);
                bR = *(const float4*)(brow + off);
            }
#pragma unroll
            for (int k = 0; k < 16; k++) {
                float4 a0 = *(const float4*)&As[cur][k][tm * 8];
                float4 a1 = *(const float4*)&As[cur][k][tm * 8 + 4];
                unsigned long long bv = *(const unsigned long long*)&Bs[cur][k][tn * 2];
                fma2(acc[0], pk2(a0.x), bv);
                fma2(acc[1], pk2(a0.y), bv);
                fma2(acc[2], pk2(a0.z), bv);
                fma2(acc[3], pk2(a0.w), bv);
                fma2(acc[4], pk2(a1.x), bv);
                fma2(acc[5], pk2(a1.y), bv);
                fma2(acc[6], pk2(a1.z), bv);
                fma2(acc[7], pk2(a1.w), bv);
            }
            __syncthreads();
        }

        // epilogue: exchange gate halves within lane pair, finalize 4 batches
        const float4 bc = *(const float4*)&g_bc[u * 4];
#pragma unroll
        for (int i = 0; i < 4; i++) {
            unsigned long long send = par ? acc[i] : acc[4 + i];
            unsigned long long recv = __shfl_xor_sync(~0u, send, 1);
            unsigned long long rz = par ? recv : acc[i];
            unsigned long long nh = par ? acc[4 + i] : recv;
            float pr, pz, pxn, phn;
            unp(rz, pr, pz);
            unp(nh, pxn, phn);
            float r = 1.f / (1.f + expf(-(pr + bc.x)));
            float z = 1.f / (1.f + expf(-(pz + bc.y)));
            float nn = tanhf(pxn + bc.z + r * (phn + bc.w));
            const int b = m0 + tm * 8 + par * 4 + i;
            g_hist[((size_t)b * SS + t) * HH + u] = (1.f - z) * nn + z * hp[i];
        }

        // grid barrier (128 co-resident blocks)
        __syncthreads();
        if (tid == 0) {
            gen++;
            __threadfence();
            unsigned prev = atomicAdd(&g_arr, 1u);
            if (prev == NBLK - 1) {
                g_arr = 0u;
                __threadfence();
                atomicExch(&g_rel, gen);
            } else {
                while (*(volatile unsigned*)&g_rel < gen) {}
                __threadfence();
            }
        }
        __syncthreads();
    }
#undef STORE_A
#undef STORE_B
}

// ---------------- batched attention + output -------------------------------------
// 1024 blocks = 128 b x 8 t-tiles(64). Online softmax over s (length-masked),
// accumulating only the 2 projected scalars per (b,t).
__global__ void __launch_bounds__(256) att_kernel(const float* __restrict__ enc,
                                                  const float* __restrict__ Wp,
                                                  const float* __restrict__ bp,
                                                  const int* __restrict__ lens,
                                                  float* __restrict__ out) {
    __shared__ float As[16][68];
    __shared__ float Bs[16][68];
    __shared__ float ec_s[64][2];
    const int bb = blockIdx.x >> 3;
    const int t0 = (blockIdx.x & 7) << 6;
    const int tid = threadIdx.x;
    const int ty = tid >> 4, tx = tid & 15;
    const int len = lens[bb];

    // hidden-state part of the projection: ph[j] = Wp[j,1024:] . h_t
    float ph0[4], ph1[4];
#pragma unroll
    for (int i = 0; i < 4; i++) {
        const int t = t0 + ty * 4 + i;
        const float* h = g_hist + ((size_t)bb * SS + t) * HH + tx * 64;
        float s0 = 0.f, s1 = 0.f;
#pragma unroll
        for (int c = 0; c < 16; c++) {
            float4 hv = *(const float4*)(h + c * 4);
            float4 w0 = *(const float4*)(Wp + 1024 + tx * 64 + c * 4);
            float4 w1 = *(const float4*)(Wp + 3072 + tx * 64 + c * 4);
            s0 += hv.x * w0.x + hv.y * w0.y + hv.z * w0.z + hv.w * w0.w;
            s1 += hv.x * w1.x + hv.y * w1.y + hv.z * w1.z + hv.w * w1.w;
        }
#pragma unroll
        for (int o = 8; o; o >>= 1) {
            s0 += __shfl_xor_sync(~0u, s0, o);
            s1 += __shfl_xor_sync(~0u, s1, o);
        }
        ph0[i] = s0; ph1[i] = s1;
    }

    float m[4], l[4], a0[4], a1[4];
#pragma unroll
    for (int i = 0; i < 4; i++) { m[i] = -1e30f; l[i] = 0.f; a0[i] = 0.f; a1[i] = 0.f; }

    const int am = tid >> 2, ak4 = (tid & 3) << 2;
    const float* hrow = g_hist + ((size_t)bb * SS + t0 + am) * HH + ak4;

    for (int sbase = 0; sbase < len; sbase += 64) {
        __syncthreads();
        if (tid < 64) {
            float2 e = *(const float2*)&g_ec[((size_t)bb * SS + sbase + tid) * 2];
            ec_s[tid][0] = e.x; ec_s[tid][1] = e.y;
        }
        const float* erow = enc + ((size_t)(sbase + am) * BB + bb) * HH + ak4;
        unsigned long long sc[4][2];
#pragma unroll
        for (int i = 0; i < 4; i++) { sc[i][0] = 0ull; sc[i][1] = 0ull; }

        for (int c = 0; c < 64; c++) {
            __syncthreads();
            float4 a4 = *(const float4*)(hrow + c * 16);
            As[ak4 + 0][am] = a4.x; As[ak4 + 1][am] = a4.y;
            As[ak4 + 2][am] = a4.z; As[ak4 + 3][am] = a4.w;
            float4 b4 = *(const float4*)(erow + c * 16);
            Bs[ak4 + 0][am] = b4.x; Bs[ak4 + 1][am] = b4.y;
            Bs[ak4 + 2][am] = b4.z; Bs[ak4 + 3][am] = b4.w;
            __syncthreads();
#pragma unroll
            for (int k = 0; k < 16; k++) {
                float4 av = *(const float4*)&As[k][ty * 4];
                ulonglong2 bpv = *(const ulonglong2*)&Bs[k][tx * 4];
                unsigned long long ax = pk2(av.x), ay = pk2(av.y);
                unsigned long long az = pk2(av.z), aw = pk2(av.w);
                fma2(sc[0][0], ax, bpv.x); fma2(sc[0][1], ax, bpv.y);
                fma2(sc[1][0], ay, bpv.x); fma2(sc[1][1], ay, bpv.y);
                fma2(sc[2][0], az, bpv.x); fma2(sc[2][1], az, bpv.y);
                fma2(sc[3][0], aw, bpv.x); fma2(sc[3][1], aw, bpv.y);
            }
        }

#pragma unroll
        for (int i = 0; i < 4; i++) {
            float s4[4];
            unp(sc[i][0], s4[0], s4[1]);
            unp(sc[i][1], s4[2], s4[3]);
#pragma unroll
            for (int j = 0; j < 4; j++)
                if (sbase + tx * 4 + j >= len) s4[j] = -1e30f;
            float cm = fmaxf(fmaxf(s4[0], s4[1]), fmaxf(s4[2], s4[3]));
#pragma unroll
            for (int o = 8; o; o >>= 1) cm = fmaxf(cm, __shfl_xor_sync(~0u, cm, o));
            const float mn = fmaxf(m[i], cm);
            const float alpha = __expf(m[i] - mn);
            float ws = 0.f, w0 = 0.f, w1 = 0.f;
#pragma unroll
            for (int j = 0; j < 4; j++) {
                float w = __expf(s4[j] - mn);
                ws += w;
                w0 += w * ec_s[tx * 4 + j][0];
                w1 += w * ec_s[tx * 4 + j][1];
            }
#pragma unroll
            for (int o = 8; o; o >>= 1) {
                ws += __shfl_xor_sync(~0u, ws, o);
                w0 += __shfl_xor_sync(~0u, w0, o);
                w1 += __shfl_xor_sync(~0u, w1, o);
            }
            l[i] = l[i] * alpha + ws;
            a0[i] = a0[i] * alpha + w0;
            a1[i] = a1[i] * alpha + w1;
            m[i] = mn;
        }
    }

    if (tx == 0) {
#pragma unroll
        for (int i = 0; i < 4; i++) {
            const int t = t0 + ty * 4 + i;
            const float inv = 1.f / l[i];
            out[((size_t)bb * SS + t) * 2 + 0] = a0[i] * inv + ph0[i] + bp[0];
            out[((size_t)bb * SS + t) * 2 + 1] = a1[i] * inv + ph1[i] + bp[1];
        }
    }
}

extern "C" void kernel_launch(void* const* d_in, const int* in_sizes, int n_in,
                              void* d_out, int out_size) {
    const float* enc  = (const float*)d_in[0];
    const float* last = (const float*)d_in[1];
    const float* Wih  = (const float*)d_in[2];
    const float* Whh  = (const float*)d_in[3];
    const float* bih  = (const float*)d_in[4];
    const float* bhh  = (const float*)d_in[5];
    const float* Wp   = (const float*)d_in[6];
    const float* bp   = (const float*)d_in[7];
    const int*   lens = (const int*)d_in[8];
    float* out = (float*)d_out;

    prep_kernel<<<4096, 256>>>(Wih, Whh, bih, bhh, last);
    ec_kernel<<<256, 256>>>(enc, Wp);
    rec_kernel<<<NBLK, 256>>>();
    att_kernel<<<1024, 256>>>(enc, Wp, bp, lens, out);
}

// round 11
// speedup vs baseline: 1.2092x; 1.2092x over previous
#include <cuda_runtime.h>
#include <math.h>

#define SS 512
#define BB 128
#define HH 1024
#define G4 4096
#define NBLK 128

// ---------------- static device scratch (no runtime allocation) ------------------
__device__ float g_Wcat[(size_t)G4 * HH];   // interleaved combined weights (t>=1)
__device__ float g_W0cat[(size_t)G4 * HH];  // interleaved step-0 weights (x=0)
__device__ float g_bc[G4];                  // interleaved combined biases
__device__ float g_h0[BB * HH];             // initial hidden state
__device__ float g_hist[(size_t)BB * SS * HH]; // h_t history [b][t][h]
__device__ float g_ec[BB * SS * 2];         // enc projected through Wp ctx rows [b][s][2]
__device__ unsigned g_arr;                  // grid-barrier arrive counter
__device__ unsigned g_rel;                  // grid-barrier release generation

// ---------------- f32x2 packed helpers -------------------------------------------
__device__ __forceinline__ unsigned long long pk2(float x) {
    unsigned long long r;
    asm("mov.b64 %0, {%1, %1};" : "=l"(r) : "f"(x));
    return r;
}
__device__ __forceinline__ void fma2(unsigned long long& d,
                                     unsigned long long a, unsigned long long b) {
    asm("fma.rn.f32x2 %0, %1, %2, %0;" : "+l"(d) : "l"(a), "l"(b));
}
__device__ __forceinline__ void add2(unsigned long long& d, unsigned long long a) {
    asm("add.rn.f32x2 %0, %0, %1;" : "+l"(d) : "l"(a));
}
__device__ __forceinline__ void unp(unsigned long long v, float& a, float& b) {
    asm("mov.b64 {%0, %1}, %2;" : "=f"(a), "=f"(b) : "l"(v));
}

// ---------------- prep: interleaved weights/biases, h0, barrier reset ------------
// interleaved col n = u*4 + g, gate g in {0:r, 1:z, 2:xn, 3:hn}
__global__ void prep_kernel(const float* __restrict__ Wih, const float* __restrict__ Whh,
                            const float* __restrict__ bih, const float* __restrict__ bhh,
                            const float* __restrict__ last) {
    const size_t total = (size_t)G4 * HH;
    const size_t tid0 = (size_t)blockIdx.x * blockDim.x + threadIdx.x;
    if (tid0 == 0) { g_arr = 0u; g_rel = 0u; }
    for (size_t idx = tid0; idx < total; idx += (size_t)gridDim.x * blockDim.x) {
        const int n = (int)(idx >> 10), k = (int)(idx & 1023);
        const int u = n >> 2, g = n & 3;
        float wc, w0;
        if (g == 0)      { float a = Wih[(size_t)u * HH + k],            b = Whh[(size_t)u * HH + k];            wc = a + b; w0 = b; }
        else if (g == 1) { float a = Wih[(size_t)(HH + u) * HH + k],     b = Whh[(size_t)(HH + u) * HH + k];     wc = a + b; w0 = b; }
        else if (g == 2) { wc = Wih[(size_t)(2 * HH + u) * HH + k];      w0 = 0.f; }
        else             { float b = Whh[(size_t)(2 * HH + u) * HH + k]; wc = b;    w0 = b; }
        g_Wcat[idx] = wc;
        g_W0cat[idx] = w0;
        if (k == 0) {
            float bc;
            if (g == 0)      bc = bih[u] + bhh[u];
            else if (g == 1) bc = bih[HH + u] + bhh[HH + u];
            else if (g == 2) bc = bih[2 * HH + u];
            else             bc = bhh[2 * HH + u];
            g_bc[n] = bc;
        }
        if (idx < (size_t)BB * HH) g_h0[idx] = last[idx];
    }
}

// ---------------- ec: g_ec[b][s][j] = Wp[j,:1024] . enc[s][b][:] -----------------
__global__ void __launch_bounds__(256) ec_kernel(const float* __restrict__ enc,
                                                 const float* __restrict__ Wp) {
    const int gw = (blockIdx.x * 256 + threadIdx.x) >> 5;   // 0..2047
    const int l = threadIdx.x & 31;
    for (int rr = 0; rr < 32; rr++) {
        const int row = gw * 32 + rr;                        // = s*BB + b
        const int s = row >> 7, b = row & 127;
        const float* e = enc + (size_t)row * HH;
        float p0 = 0.f, p1 = 0.f;
#pragma unroll
        for (int c = 0; c < 8; c++) {
            float4 v  = *(const float4*)(e + l * 4 + c * 128);
            float4 w0 = *(const float4*)(Wp + l * 4 + c * 128);
            float4 w1 = *(const float4*)(Wp + 2048 + l * 4 + c * 128);
            p0 += v.x * w0.x + v.y * w0.y + v.z * w0.z + v.w * w0.w;
            p1 += v.x * w1.x + v.y * w1.y + v.z * w1.z + v.w * w1.w;
        }
#pragma unroll
        for (int o = 16; o; o >>= 1) {
            p0 += __shfl_xor_sync(~0u, p0, o);
            p1 += __shfl_xor_sync(~0u, p1, o);
        }
        if (l == 0) {
            g_ec[((size_t)b * SS + s) * 2 + 0] = p0;
            g_ec[((size_t)b * SS + s) * 2 + 1] = p1;
        }
    }
}

// ---------------- persistent recurrence: 512 steps, 1 grid barrier each ----------
// 128 blocks x 256 threads. Block tile: 32m x 128n. Two K-split groups of 128
// threads (k in [0,512) / [512,1024)), each with R7's 8m x 4n thread tile and its
// own double-buffered smem -> 8 warps/SM hide latency while LDS wf/FMA = 0.9.
// Warp layout (mg, nl): warp owns a 32-col n-subrange -> B fragment = 1 wavefront.
// Per-step: partial accs combined via smem (add.rn.f32x2), gate fusion by group 0.
__global__ void __launch_bounds__(256, 1) rec_kernel() {
    __shared__ float As[2][2][16][36];    // [grp][buf][k][m]
    __shared__ float Bs[2][2][16][132];   // [grp][buf][k][n]
    const int tid = threadIdx.x;
    const int grp = tid >> 7;             // k-split group 0/1
    const int gtid = tid & 127;
    const int blk = blockIdx.x;
    const int m0 = (blk >> 5) * 32;       // 4 m-tiles
    const int n0 = (blk & 31) * 128;      // 32 n-tiles
    const int w  = gtid >> 5;             // warp in group -> n-subrange w*32
    const int mg = (gtid >> 3) & 3;       // m-group -> rows mg*8..+7
    const int nl = gtid & 7;              // n-lane -> cols w*32+nl*4
    const int u  = (n0 >> 2) + w * 8 + nl; // hidden unit owned (gate quad)
    const int ar = gtid >> 2;             // A-loader row 0..31
    const int akc = (gtid & 3) << 2;      // A-loader k-col
    const int br = gtid >> 2;             // B-loader rows br+32j
    const int bkc = (gtid & 3) << 2;      // B-loader k-col
    const int kb = grp << 9;              // k base: 0 or 512
    unsigned gen = 0;

#define STORE_A(buf, v)                                                   \
    { As[grp][buf][akc + 0][ar] = (v).x; As[grp][buf][akc + 1][ar] = (v).y; \
      As[grp][buf][akc + 2][ar] = (v).z; As[grp][buf][akc + 3][ar] = (v).w; }
#define STORE_B(buf, v, j)                                                \
    { Bs[grp][buf][bkc + 0][br + 32 * (j)] = (v).x; Bs[grp][buf][bkc + 1][br + 32 * (j)] = (v).y; \
      Bs[grp][buf][bkc + 2][br + 32 * (j)] = (v).z; Bs[grp][buf][bkc + 3][br + 32 * (j)] = (v).w; }

    for (int t = 0; t < SS; t++) {
        const float* W = (t == 0) ? g_W0cat : g_Wcat;
        const float* arow = ((t == 0) ? (g_h0 + (size_t)(m0 + ar) * HH)
                                      : (g_hist + ((size_t)(m0 + ar) * SS + (t - 1)) * HH)) + kb + akc;
        const float* brow = W + (size_t)(n0 + br) * HH + kb + bkc;

        // group 0 prefetches h_prev for its epilogue rows (hidden under K-loop)
        float hp[8];
        if (grp == 0) {
#pragma unroll
            for (int i = 0; i < 8; i++) {
                const int b = m0 + mg * 8 + i;
                hp[i] = (t == 0) ? g_h0[(size_t)b * HH + u]
                                 : g_hist[((size_t)b * SS + (t - 1)) * HH + u];
            }
        }

        // prologue: chunk 0 -> buf0, chunk 1 -> regs
        float4 aR = *(const float4*)arow;
        float4 bR0 = *(const float4*)(brow);
        float4 bR1 = *(const float4*)(brow + 32 * HH);
        float4 bR2 = *(const float4*)(brow + 64 * HH);
        float4 bR3 = *(const float4*)(brow + 96 * HH);
        STORE_A(0, aR);
        STORE_B(0, bR0, 0); STORE_B(0, bR1, 1); STORE_B(0, bR2, 2); STORE_B(0, bR3, 3);
        aR = *(const float4*)(arow + 16);
        bR0 = *(const float4*)(brow + 16);
        bR1 = *(const float4*)(brow + 32 * HH + 16);
        bR2 = *(const float4*)(brow + 64 * HH + 16);
        bR3 = *(const float4*)(brow + 96 * HH + 16);
        __syncthreads();

        unsigned long long acc[8][2];
#pragma unroll
        for (int i = 0; i < 8; i++) { acc[i][0] = 0ull; acc[i][1] = 0ull; }

        for (int c = 0; c < 32; c++) {          // 32 chunks of 16 k per group
            const int cur = c & 1;
            if (c < 31) {
                STORE_A(cur ^ 1, aR);
                STORE_B(cur ^ 1, bR0, 0); STORE_B(cur ^ 1, bR1, 1);
                STORE_B(cur ^ 1, bR2, 2); STORE_B(cur ^ 1, bR3, 3);
            }
            if (c < 30) {
                const int off = (c + 2) * 16;
                aR = *(const float4*)(arow + off);
                bR0 = *(const float4*)(brow + off);
                bR1 = *(const float4*)(brow + 32 * HH + off);
                bR2 = *(const float4*)(brow + 64 * HH + off);
                bR3 = *(const float4*)(brow + 96 * HH + off);
            }
#pragma unroll
            for (int k = 0; k < 16; k++) {
                float4 a0 = *(const float4*)&As[grp][cur][k][mg * 8];
                float4 a1 = *(const float4*)&As[grp][cur][k][mg * 8 + 4];
                ulonglong2 bv = *(const ulonglong2*)&Bs[grp][cur][k][w * 32 + nl * 4];
                unsigned long long p;
                p = pk2(a0.x); fma2(acc[0][0], p, bv.x); fma2(acc[0][1], p, bv.y);
                p = pk2(a0.y); fma2(acc[1][0], p, bv.x); fma2(acc[1][1], p, bv.y);
                p = pk2(a0.z); fma2(acc[2][0], p, bv.x); fma2(acc[2][1], p, bv.y);
                p = pk2(a0.w); fma2(acc[3][0], p, bv.x); fma2(acc[3][1], p, bv.y);
                p = pk2(a1.x); fma2(acc[4][0], p, bv.x); fma2(acc[4][1], p, bv.y);
                p = pk2(a1.y); fma2(acc[5][0], p, bv.x); fma2(acc[5][1], p, bv.y);
                p = pk2(a1.z); fma2(acc[6][0], p, bv.x); fma2(acc[6][1], p, bv.y);
                p = pk2(a1.w); fma2(acc[7][0], p, bv.x); fma2(acc[7][1], p, bv.y);
            }
            __syncthreads();
        }

        // K-split reduction: group 1 stages partials in smem (alias Bs), group 0 adds
        unsigned long long* red = (unsigned long long*)&Bs[0][0][0][0];
        if (grp == 1) {
#pragma unroll
            for (int i = 0; i < 8; i++) {
                red[gtid * 17 + i * 2 + 0] = acc[i][0];
                red[gtid * 17 + i * 2 + 1] = acc[i][1];
            }
        }
        __syncthreads();
        if (grp == 0) {
#pragma unroll
            for (int i = 0; i < 8; i++) {
                add2(acc[i][0], red[gtid * 17 + i * 2 + 0]);
                add2(acc[i][1], red[gtid * 17 + i * 2 + 1]);
            }
            // gate fusion: this thread owns unit u for 8 batch rows
            const float4 bc = *(const float4*)&g_bc[u * 4];
#pragma unroll
            for (int i = 0; i < 8; i++) {
                const int b = m0 + mg * 8 + i;
                float pr, pz, pxn, phn;
                unp(acc[i][0], pr, pz);
                unp(acc[i][1], pxn, phn);
                float r = 1.f / (1.f + expf(-(pr + bc.x)));
                float z = 1.f / (1.f + expf(-(pz + bc.y)));
                float nn = tanhf(pxn + bc.z + r * (phn + bc.w));
                g_hist[((size_t)b * SS + t) * HH + u] = (1.f - z) * nn + z * hp[i];
            }
        }

        // grid barrier (128 co-resident blocks)
        __syncthreads();
        if (tid == 0) {
            gen++;
            __threadfence();
            unsigned prev = atomicAdd(&g_arr, 1u);
            if (prev == NBLK - 1) {
                g_arr = 0u;
                __threadfence();
                atomicExch(&g_rel, gen);
            } else {
                while (*(volatile unsigned*)&g_rel < gen) {}
                __threadfence();
            }
        }
        __syncthreads();
    }
#undef STORE_A
#undef STORE_B
}

// ---------------- batched attention + output -------------------------------------
// 1024 blocks = 128 b x 8 t-tiles(64). Online softmax over s (length-masked),
// accumulating only the 2 projected scalars per (b,t).
__global__ void __launch_bounds__(256) att_kernel(const float* __restrict__ enc,
                                                  const float* __restrict__ Wp,
                                                  const float* __restrict__ bp,
                                                  const int* __restrict__ lens,
                                                  float* __restrict__ out) {
    __shared__ float As[16][68];
    __shared__ float Bs[16][68];
    __shared__ float ec_s[64][2];
    const int bb = blockIdx.x >> 3;
    const int t0 = (blockIdx.x & 7) << 6;
    const int tid = threadIdx.x;
    const int ty = tid >> 4, tx = tid & 15;
    const int len = lens[bb];

    // hidden-state part of the projection: ph[j] = Wp[j,1024:] . h_t
    float ph0[4], ph1[4];
#pragma unroll
    for (int i = 0; i < 4; i++) {
        const int t = t0 + ty * 4 + i;
        const float* h = g_hist + ((size_t)bb * SS + t) * HH + tx * 64;
        float s0 = 0.f, s1 = 0.f;
#pragma unroll
        for (int c = 0; c < 16; c++) {
            float4 hv = *(const float4*)(h + c * 4);
            float4 w0 = *(const float4*)(Wp + 1024 + tx * 64 + c * 4);
            float4 w1 = *(const float4*)(Wp + 3072 + tx * 64 + c * 4);
            s0 += hv.x * w0.x + hv.y * w0.y + hv.z * w0.z + hv.w * w0.w;
            s1 += hv.x * w1.x + hv.y * w1.y + hv.z * w1.z + hv.w * w1.w;
        }
#pragma unroll
        for (int o = 8; o; o >>= 1) {
            s0 += __shfl_xor_sync(~0u, s0, o);
            s1 += __shfl_xor_sync(~0u, s1, o);
        }
        ph0[i] = s0; ph1[i] = s1;
    }

    float m[4], l[4], a0[4], a1[4];
#pragma unroll
    for (int i = 0; i < 4; i++) { m[i] = -1e30f; l[i] = 0.f; a0[i] = 0.f; a1[i] = 0.f; }

    const int am = tid >> 2, ak4 = (tid & 3) << 2;
    const float* hrow = g_hist + ((size_t)bb * SS + t0 + am) * HH + ak4;

    for (int sbase = 0; sbase < len; sbase += 64) {
        __syncthreads();
        if (tid < 64) {
            float2 e = *(const float2*)&g_ec[((size_t)bb * SS + sbase + tid) * 2];
            ec_s[tid][0] = e.x; ec_s[tid][1] = e.y;
        }
        const float* erow = enc + ((size_t)(sbase + am) * BB + bb) * HH + ak4;
        unsigned long long sc[4][2];
#pragma unroll
        for (int i = 0; i < 4; i++) { sc[i][0] = 0ull; sc[i][1] = 0ull; }

        for (int c = 0; c < 64; c++) {
            __syncthreads();
            float4 a4 = *(const float4*)(hrow + c * 16);
            As[ak4 + 0][am] = a4.x; As[ak4 + 1][am] = a4.y;
            As[ak4 + 2][am] = a4.z; As[ak4 + 3][am] = a4.w;
            float4 b4 = *(const float4*)(erow + c * 16);
            Bs[ak4 + 0][am] = b4.x; Bs[ak4 + 1][am] = b4.y;
            Bs[ak4 + 2][am] = b4.z; Bs[ak4 + 3][am] = b4.w;
            __syncthreads();
#pragma unroll
            for (int k = 0; k < 16; k++) {
                float4 av = *(const float4*)&As[k][ty * 4];
                ulonglong2 bpv = *(const ulonglong2*)&Bs[k][tx * 4];
                unsigned long long ax = pk2(av.x), ay = pk2(av.y);
                unsigned long long az = pk2(av.z), aw = pk2(av.w);
                fma2(sc[0][0], ax, bpv.x); fma2(sc[0][1], ax, bpv.y);
                fma2(sc[1][0], ay, bpv.x); fma2(sc[1][1], ay, bpv.y);
                fma2(sc[2][0], az, bpv.x); fma2(sc[2][1], az, bpv.y);
                fma2(sc[3][0], aw, bpv.x); fma2(sc[3][1], aw, bpv.y);
            }
        }

#pragma unroll
        for (int i = 0; i < 4; i++) {
            float s4[4];
            unp(sc[i][0], s4[0], s4[1]);
            unp(sc[i][1], s4[2], s4[3]);
#pragma unroll
            for (int j = 0; j < 4; j++)
                if (sbase + tx * 4 + j >= len) s4[j] = -1e30f;
            float cm = fmaxf(fmaxf(s4[0], s4[1]), fmaxf(s4[2], s4[3]));
#pragma unroll
            for (int o = 8; o; o >>= 1) cm = fmaxf(cm, __shfl_xor_sync(~0u, cm, o));
            const float mn = fmaxf(m[i], cm);
            const float alpha = __expf(m[i] - mn);
            float ws = 0.f, w0 = 0.f, w1 = 0.f;
#pragma unroll
            for (int j = 0; j < 4; j++) {
                float w = __expf(s4[j] - mn);
                ws += w;
                w0 += w * ec_s[tx * 4 + j][0];
                w1 += w * ec_s[tx * 4 + j][1];
            }
#pragma unroll
            for (int o = 8; o; o >>= 1) {
                ws += __shfl_xor_sync(~0u, ws, o);
                w0 += __shfl_xor_sync(~0u, w0, o);
                w1 += __shfl_xor_sync(~0u, w1, o);
            }
            l[i] = l[i] * alpha + ws;
            a0[i] = a0[i] * alpha + w0;
            a1[i] = a1[i] * alpha + w1;
            m[i] = mn;
        }
    }

    if (tx == 0) {
#pragma unroll
        for (int i = 0; i < 4; i++) {
            const int t = t0 + ty * 4 + i;
            const float inv = 1.f / l[i];
            out[((size_t)bb * SS + t) * 2 + 0] = a0[i] * inv + ph0[i] + bp[0];
            out[((size_t)bb * SS + t) * 2 + 1] = a1[i] * inv + ph1[i] + bp[1];
        }
    }
}

extern "C" void kernel_launch(void* const* d_in, const int* in_sizes, int n_in,
                              void* d_out, int out_size) {
    const float* enc  = (const float*)d_in[0];
    const float* last = (const float*)d_in[1];
    const float* Wih  = (const float*)d_in[2];
    const float* Whh  = (const float*)d_in[3];
    const float* bih  = (const float*)d_in[4];
    const float* bhh  = (const float*)d_in[5];
    const float* Wp   = (const float*)d_in[6];
    const float* bp   = (const float*)d_in[7];
    const int*   lens = (const int*)d_in[8];
    float* out = (float*)d_out;

    prep_kernel<<<4096, 256>>>(Wih, Whh, bih, bhh, last);
    ec_kernel<<<256, 256>>>(enc, Wp);
    rec_kernel<<<NBLK, 256>>>();
    att_kernel<<<1024, 256>>>(enc, Wp, bp, lens, out);
}

// round 13
// speedup vs baseline: 2.2611x; 1.8700x over previous
#include <cuda_runtime.h>
#include <cuda_bf16.h>
#include <math.h>
#include <stdint.h>

#define SS 512
#define BB 128
#define HH 1024
#define G4 4096
#define NBLK 128

// rec smem: W images [0,131072); A chunk buffers [131072, 196608)
#define SMW 0
#define SMA 131072
#define ABUF 32768
#define SM_TOTAL 196608

// ---------------- static device scratch -----------------------------------------
__device__ float g_W0f[(size_t)G4 * HH];                  // step-0 interleaved W (fp32)
__device__ __align__(16) __nv_bfloat16 g_Wimg[NBLK][2][32 * 1024]; // Wcat bf16 hi/lo, swizzled
__device__ __align__(16) __nv_bfloat16 g_himg[2][16][128 * 64];    // h bf16 hi/lo A-image
__device__ float g_bc[G4];                  // interleaved combined biases
__device__ float g_h0[BB * HH];             // initial hidden fp32
__device__ float g_g[BB * G4];              // step-0 gate pre-activations
__device__ float g_hist[(size_t)BB * SS * HH]; // h_t history [b][t][h]
__device__ float g_ec[BB * SS * 2];         // enc @ Wp ctx rows
__device__ unsigned g_arr, g_rel;           // grid barrier

// ---------------- f32x2 helpers (att kernel) -------------------------------------
__device__ __forceinline__ unsigned long long pk2(float x) {
    unsigned long long r;
    asm("mov.b64 %0, {%1, %1};" : "=l"(r) : "f"(x));
    return r;
}
__device__ __forceinline__ void fma2(unsigned long long& d,
                                     unsigned long long a, unsigned long long b) {
    asm("fma.rn.f32x2 %0, %1, %2, %0;" : "+l"(d) : "l"(a), "l"(b));
}
__device__ __forceinline__ void unp(unsigned long long v, float& a, float& b) {
    asm("mov.b64 {%0, %1}, %2;" : "=f"(a), "=f"(b) : "l"(v));
}

// ---------------- mma/ldmatrix helpers --------------------------------------------
__device__ __forceinline__ uint32_t smem_u32(const void* p) {
    uint32_t a;
    asm("{ .reg .u64 t; cvta.to.shared.u64 t, %1; cvt.u32.u64 %0, t; }" : "=r"(a) : "l"(p));
    return a;
}
#define LDSM4(r, a)                                                                  \
    asm volatile("ldmatrix.sync.aligned.m8n8.x4.shared.b16 {%0,%1,%2,%3}, [%4];"     \
        : "=r"((r)[0]), "=r"((r)[1]), "=r"((r)[2]), "=r"((r)[3]) : "r"(a))
#define LDSM2(r, a)                                                                  \
    asm volatile("ldmatrix.sync.aligned.m8n8.x2.shared.b16 {%0,%1}, [%2];"           \
        : "=r"((r)[0]), "=r"((r)[1]) : "r"(a))
#define MMA(c, a, b)                                                                 \
    asm volatile("mma.sync.aligned.m16n8k16.row.col.f32.bf16.bf16.f32 "              \
        "{%0,%1,%2,%3},{%4,%5,%6,%7},{%8,%9},{%0,%1,%2,%3};"                         \
        : "+f"((c)[0]), "+f"((c)[1]), "+f"((c)[2]), "+f"((c)[3])                     \
        : "r"((a)[0]), "r"((a)[1]), "r"((a)[2]), "r"((a)[3]), "r"((b)[0]), "r"((b)[1]))

// W image element offset for (nl in [0,32), k in [0,1024)); j = k>>3
__host__ __device__ __forceinline__ int wimg_off(int nl, int k) {
    int j = k >> 3;
    return nl * 1024 + (j >> 3) * 64 + (((j & 7) ^ (nl & 7)) << 3) + (k & 7);
}
// h image element offset within a chunk for (m in [0,128), kc in [0,64)); j = kc>>3
__host__ __device__ __forceinline__ int himg_off(int m, int kc) {
    int j = kc >> 3;
    return m * 64 + ((j ^ (m & 7)) << 3) + (kc & 7);
}

// ---------------- prep ------------------------------------------------------------
// interleaved gate col n = u*4 + g, g in {0:r, 1:z, 2:xn, 3:hn}
__global__ void prep_kernel(const float* __restrict__ Wih, const float* __restrict__ Whh,
                            const float* __restrict__ bih, const float* __restrict__ bhh,
                            const float* __restrict__ last) {
    const size_t total = (size_t)G4 * HH;
    const size_t t0 = (size_t)blockIdx.x * blockDim.x + threadIdx.x;
    if (t0 == 0) { g_arr = 0u; g_rel = 0u; }
    for (size_t idx = t0; idx < total; idx += (size_t)gridDim.x * blockDim.x) {
        const int n = (int)(idx >> 10), k = (int)(idx & 1023);
        const int u = n >> 2, g = n & 3;
        float wc, w0;
        if (g == 0)      { float a = Wih[(size_t)u * HH + k],            b = Whh[(size_t)u * HH + k];            wc = a + b; w0 = b; }
        else if (g == 1) { float a = Wih[(size_t)(HH + u) * HH + k],     b = Whh[(size_t)(HH + u) * HH + k];     wc = a + b; w0 = b; }
        else if (g == 2) { wc = Wih[(size_t)(2 * HH + u) * HH + k];      w0 = 0.f; }
        else             { float b = Whh[(size_t)(2 * HH + u) * HH + k]; wc = b;    w0 = b; }
        g_W0f[idx] = w0;
        const int bn = n >> 5, nl = n & 31;
        const int off = wimg_off(nl, k);
        __nv_bfloat16 hi = __float2bfloat16(wc);
        g_Wimg[bn][0][off] = hi;
        g_Wimg[bn][1][off] = __float2bfloat16(wc - __bfloat162float(hi));
        if (k == 0) {
            float bc;
            if (g == 0)      bc = bih[u] + bhh[u];
            else if (g == 1) bc = bih[HH + u] + bhh[HH + u];
            else if (g == 2) bc = bih[2 * HH + u];
            else             bc = bhh[2 * HH + u];
            g_bc[n] = bc;
        }
        if (idx < (size_t)BB * HH) g_h0[idx] = last[idx];
    }
}

// ---------------- step-0 GEMM (one shot, fp32 SIMT): g_g = g_h0 @ g_W0f^T ---------
__global__ void __launch_bounds__(128) gemm0_kernel() {
    __shared__ float As[2][16][68];
    __shared__ float Bs[2][16][68];
    const int tid = threadIdx.x;
    const int bn = blockIdx.x * 64;
    const int bm = blockIdx.y * 64;
    const int lr = tid >> 2;
    const int kc = (tid & 3) << 2;
    const float* A0 = g_h0 + (size_t)(bm + lr) * HH + kc;
    const float* A1 = A0 + 32 * HH;
    const float* B0 = g_W0f + (size_t)(bn + lr) * HH + kc;
    const float* B1 = B0 + 32 * HH;

    float4 a0 = *(const float4*)A0;
    float4 a1 = *(const float4*)A1;
    float4 b0 = *(const float4*)B0;
    float4 b1 = *(const float4*)B1;

#define STORE_TILE(buf, A0v, A1v, B0v, B1v)                          \
    {                                                                \
        As[buf][kc+0][lr]    = A0v.x; As[buf][kc+1][lr]    = A0v.y;  \
        As[buf][kc+2][lr]    = A0v.z; As[buf][kc+3][lr]    = A0v.w;  \
        As[buf][kc+0][lr+32] = A1v.x; As[buf][kc+1][lr+32] = A1v.y;  \
        As[buf][kc+2][lr+32] = A1v.z; As[buf][kc+3][lr+32] = A1v.w;  \
        Bs[buf][kc+0][lr]    = B0v.x; Bs[buf][kc+1][lr]    = B0v.y;  \
        Bs[buf][kc+2][lr]    = B0v.z; Bs[buf][kc+3][lr]    = B0v.w;  \
        Bs[buf][kc+0][lr+32] = B1v.x; Bs[buf][kc+1][lr+32] = B1v.y;  \
        Bs[buf][kc+2][lr+32] = B1v.z; Bs[buf][kc+3][lr+32] = B1v.w;  \
    }
    STORE_TILE(0, a0, a1, b0, b1);
    __syncthreads();
    float acc[8][4];
#pragma unroll
    for (int i = 0; i < 8; i++)
#pragma unroll
        for (int j = 0; j < 4; j++) acc[i][j] = 0.f;
    const int tm = (tid >> 4) << 3;
    const int tn = (tid & 15) << 2;
    for (int kt = 0; kt < 64; kt++) {
        const int cur = kt & 1;
        float4 a0n, a1n, b0n, b1n;
        if (kt < 63) {
            const int off = (kt + 1) * 16;
            a0n = *(const float4*)(A0 + off);
            a1n = *(const float4*)(A1 + off);
            b0n = *(const float4*)(B0 + off);
            b1n = *(const float4*)(B1 + off);
        }
#pragma unroll
        for (int k = 0; k < 16; k++) {
            float4 av0 = *(const float4*)&As[cur][k][tm];
            float4 av1 = *(const float4*)&As[cur][k][tm + 4];
            float4 bv  = *(const float4*)&Bs[cur][k][tn];
            float am[8] = {av0.x, av0.y, av0.z, av0.w, av1.x, av1.y, av1.z, av1.w};
            float bv4[4] = {bv.x, bv.y, bv.z, bv.w};
#pragma unroll
            for (int i = 0; i < 8; i++)
#pragma unroll
                for (int j = 0; j < 4; j++) acc[i][j] += am[i] * bv4[j];
        }
        if (kt < 63) {
            __syncthreads();
            STORE_TILE(cur ^ 1, a0n, a1n, b0n, b1n);
            __syncthreads();
        }
    }
#undef STORE_TILE
#pragma unroll
    for (int i = 0; i < 8; i++) {
        float4 v = make_float4(acc[i][0], acc[i][1], acc[i][2], acc[i][3]);
        *(float4*)&g_g[(size_t)(bm + tm + i) * G4 + bn + tn] = v;
    }
}

// ---------------- fuse0: h1 from step-0 pre-acts -> hist[:,0,:] + h image ---------
__global__ void __launch_bounds__(256) fuse0_kernel() {
    const int b = blockIdx.x;
    const int tid = threadIdx.x;
#pragma unroll
    for (int q = 0; q < 4; q++) {
        const int u = tid + q * 256;
        const float* gr = g_g + (size_t)b * G4 + u * 4;
        const float4 bc = *(const float4*)&g_bc[u * 4];
        float pr = gr[0] + bc.x, pz = gr[1] + bc.y;
        float pxn = gr[2] + bc.z, phn = gr[3] + bc.w;
        float r = 1.f / (1.f + expf(-pr));
        float z = 1.f / (1.f + expf(-pz));
        float nn = tanhf(pxn + r * phn);
        float h = (1.f - z) * nn + z * g_h0[(size_t)b * HH + u];
        g_hist[((size_t)b * SS + 0) * HH + u] = h;
        __nv_bfloat16 hi = __float2bfloat16(h);
        const int off = himg_off(b, u & 63);
        g_himg[0][u >> 6][off] = hi;
        g_himg[1][u >> 6][off] = __float2bfloat16(h - __bfloat162float(hi));
    }
}

// ---------------- ec: g_ec[b][s][j] = Wp[j,:1024] . enc[s][b][:] ------------------
__global__ void __launch_bounds__(256) ec_kernel(const float* __restrict__ enc,
                                                 const float* __restrict__ Wp) {
    const int gw = (blockIdx.x * 256 + threadIdx.x) >> 5;
    const int l = threadIdx.x & 31;
    for (int rr = 0; rr < 32; rr++) {
        const int row = gw * 32 + rr;
        const int s = row >> 7, b = row & 127;
        const float* e = enc + (size_t)row * HH;
        float p0 = 0.f, p1 = 0.f;
#pragma unroll
        for (int c = 0; c < 8; c++) {
            float4 v  = *(const float4*)(e + l * 4 + c * 128);
            float4 w0 = *(const float4*)(Wp + l * 4 + c * 128);
            float4 w1 = *(const float4*)(Wp + 2048 + l * 4 + c * 128);
            p0 += v.x * w0.x + v.y * w0.y + v.z * w0.z + v.w * w0.w;
            p1 += v.x * w1.x + v.y * w1.y + v.z * w1.z + v.w * w1.w;
        }
#pragma unroll
        for (int o = 16; o; o >>= 1) {
            p0 += __shfl_xor_sync(~0u, p0, o);
            p1 += __shfl_xor_sync(~0u, p1, o);
        }
        if (l == 0) {
            g_ec[((size_t)b * SS + s) * 2 + 0] = p0;
            g_ec[((size_t)b * SS + s) * 2 + 1] = p1;
        }
    }
}

// ---------------- persistent tensor-core recurrence (mma.sync bf16 hi/lo) ---------
// 128 blocks x 256 threads (8 warps: 4 along m x 2 along n). Block: 128m x 32 gate
// cols, K=1024 in 16 chunks of 64. W smem-resident; A double-buffered. Steps 1..511.
__global__ void __launch_bounds__(256, 1) rec_kernel() {
    extern __shared__ __align__(16) char smem[];
    const int tid = threadIdx.x;
    const int warp = tid >> 5, lane = tid & 31;
    const int mw = (warp & 3) * 32;       // warp m offset
    const int nw = (warp >> 2) * 16;      // warp n offset
    const int g = lane >> 2, tg = lane & 3;
    const int bn = blockIdx.x;
    const uint32_t sadd = smem_u32(smem);

    // W images -> smem (128KB flat copy; layout identical)
    {
        const uint4* src = (const uint4*)&g_Wimg[bn][0][0];
        uint4* dst = (uint4*)(smem + SMW);
#pragma unroll
        for (int i = 0; i < 32; i++) dst[tid + i * 256] = src[tid + i * 256];
    }

    // ldmatrix lane constants
    const int m_ld = mw + (((lane >> 3) & 1) << 3) + (lane & 7); // A row, tile 0
    const int matj = lane >> 4;                                   // A k-half
    const int aoff0 = m_ld * 128,        asw0 = m_ld & 7;
    const int aoff1 = (m_ld + 16) * 128, asw1 = (m_ld + 16) & 7;
    const int bl = lane & 15;
    const int nl0 = nw + (bl & 7), nl1 = nl0 + 8;
    const int bmat = bl >> 3;
    const uint32_t bB0 = sadd + SMW + nl0 * 2048, bB1 = sadd + SMW + nl1 * 2048;
    const int bsw0 = nl0 & 7, bsw1 = nl1 & 7;

    // epilogue bookkeeping (odd lanes finalize)
    const int parity = tg & 1;
    const int u_g0 = bn * 8 + (warp >> 2) * 4 + 0 + (tg >> 1);
    const int u_g1 = bn * 8 + (warp >> 2) * 4 + 2 + (tg >> 1);
    const float4 bc0 = *(const float4*)&g_bc[u_g0 * 4];
    const float4 bc1 = *(const float4*)&g_bc[u_g1 * 4];
    float hp[2][2][2]; // [mt][nt][rh]
#pragma unroll
    for (int mt = 0; mt < 2; mt++)
#pragma unroll
        for (int nt = 0; nt < 2; nt++)
#pragma unroll
            for (int rh = 0; rh < 2; rh++) {
                const int m = mw + mt * 16 + rh * 8 + g;
                const int u = nt ? u_g1 : u_g0;
                hp[mt][nt][rh] = g_hist[((size_t)m * SS + 0) * HH + u];
            }
    __syncthreads();

    unsigned gen = 0;
    for (int t = 1; t < SS; t++) {
        float acc[2][2][4];
#pragma unroll
        for (int i = 0; i < 2; i++)
#pragma unroll
            for (int j = 0; j < 2; j++)
#pragma unroll
                for (int q = 0; q < 4; q++) acc[i][j][q] = 0.f;

        uint4 rh4[4], rl4[4];
        // prologue: chunk1 -> regs (long latency), chunk0 -> buf0
        {
            const uint4* sh = (const uint4*)&g_himg[0][1][0];
            const uint4* sl = (const uint4*)&g_himg[1][1][0];
#pragma unroll
            for (int i = 0; i < 4; i++) { rh4[i] = __ldcg(sh + tid + i * 256); rl4[i] = __ldcg(sl + tid + i * 256); }
            const uint4* s0h = (const uint4*)&g_himg[0][0][0];
            const uint4* s0l = (const uint4*)&g_himg[1][0][0];
            uint4* dh = (uint4*)(smem + SMA);
            uint4* dl = (uint4*)(smem + SMA + 16384);
#pragma unroll
            for (int i = 0; i < 4; i++) { dh[tid + i * 256] = __ldcg(s0h + tid + i * 256); dl[tid + i * 256] = __ldcg(s0l + tid + i * 256); }
        }
        __syncthreads();

        for (int c = 0; c < 16; c++) {
            const int cur = c & 1;
            if (c < 15) {
                uint4* dh = (uint4*)(smem + SMA + (cur ^ 1) * ABUF);
                uint4* dl = (uint4*)(smem + SMA + (cur ^ 1) * ABUF + 16384);
#pragma unroll
                for (int i = 0; i < 4; i++) { dh[tid + i * 256] = rh4[i]; dl[tid + i * 256] = rl4[i]; }
            }
            if (c < 14) {
                const uint4* sh = (const uint4*)&g_himg[0][c + 2][0];
                const uint4* sl = (const uint4*)&g_himg[1][c + 2][0];
#pragma unroll
                for (int i = 0; i < 4; i++) { rh4[i] = __ldcg(sh + tid + i * 256); rl4[i] = __ldcg(sl + tid + i * 256); }
            }
            const uint32_t aH = sadd + SMA + cur * ABUF;
            const uint32_t aL = aH + 16384;
#pragma unroll
            for (int ks = 0; ks < 4; ks++) {
                uint32_t a0h[4], a1h[4], a0l[4], a1l[4];
                uint32_t b0h[2], b1h[2], b0l[2], b1l[2];
                const int ja = ks * 2 + matj;
                LDSM4(a0h, aH + aoff0 + ((ja ^ asw0) << 4));
                LDSM4(a1h, aH + aoff1 + ((ja ^ asw1) << 4));
                LDSM4(a0l, aL + aoff0 + ((ja ^ asw0) << 4));
                LDSM4(a1l, aL + aoff1 + ((ja ^ asw1) << 4));
                const int jb = ks * 2 + bmat;
                const uint32_t cOff = c * 128;
                LDSM2(b0h, bB0 + cOff + ((jb ^ bsw0) << 4));
                LDSM2(b1h, bB1 + cOff + ((jb ^ bsw1) << 4));
                LDSM2(b0l, bB0 + 65536 + cOff + ((jb ^ bsw0) << 4));
                LDSM2(b1l, bB1 + 65536 + cOff + ((jb ^ bsw1) << 4));
                MMA(acc[0][0], a0h, b0h); MMA(acc[0][1], a0h, b1h);
                MMA(acc[1][0], a1h, b0h); MMA(acc[1][1], a1h, b1h);
                MMA(acc[0][0], a0h, b0l); MMA(acc[0][1], a0h, b1l);
                MMA(acc[1][0], a1h, b0l); MMA(acc[1][1], a1h, b1l);
                MMA(acc[0][0], a0l, b0h); MMA(acc[0][1], a0l, b1h);
                MMA(acc[1][0], a1l, b0h); MMA(acc[1][1], a1l, b1h);
            }
            __syncthreads();
        }

        // exchange gate halves within lane pair; odd lanes finalize
        float rc[2][2][4];
#pragma unroll
        for (int mt = 0; mt < 2; mt++)
#pragma unroll
            for (int nt = 0; nt < 2; nt++)
#pragma unroll
                for (int q = 0; q < 4; q++)
                    rc[mt][nt][q] = __shfl_xor_sync(~0u, acc[mt][nt][q], 1);
        if (parity) {
#pragma unroll
            for (int nt = 0; nt < 2; nt++) {
                const float4 bc = nt ? bc1 : bc0;
                const int u = nt ? u_g1 : u_g0;
                const int ch = u >> 6, kc = u & 63;
#pragma unroll
                for (int mt = 0; mt < 2; mt++)
#pragma unroll
                    for (int rh = 0; rh < 2; rh++) {
                        const int m = mw + mt * 16 + rh * 8 + g;
                        float pr  = rc[mt][nt][rh * 2 + 0] + bc.x;
                        float pz  = rc[mt][nt][rh * 2 + 1] + bc.y;
                        float pxn = acc[mt][nt][rh * 2 + 0] + bc.z;
                        float phn = acc[mt][nt][rh * 2 + 1] + bc.w;
                        float r = 1.f / (1.f + expf(-pr));
                        float z = 1.f / (1.f + expf(-pz));
                        float nn = tanhf(pxn + r * phn);
                        float h = (1.f - z) * nn + z * hp[mt][nt][rh];
                        hp[mt][nt][rh] = h;
                        g_hist[((size_t)m * SS + t) * HH + u] = h;
                        __nv_bfloat16 hi = __float2bfloat16(h);
                        const int off = himg_off(m, kc);
                        g_himg[0][ch][off] = hi;
                        g_himg[1][ch][off] = __float2bfloat16(h - __bfloat162float(hi));
                    }
            }
        }

        // grid barrier (128 co-resident blocks)
        __syncthreads();
        if (tid == 0) {
            gen++;
            __threadfence();
            unsigned prev = atomicAdd(&g_arr, 1u);
            if (prev == NBLK - 1) {
                g_arr = 0u;
                __threadfence();
                atomicExch(&g_rel, gen);
            } else {
                while (*(volatile unsigned*)&g_rel < gen) {}
                __threadfence();
            }
        }
        __syncthreads();
    }
}

// ---------------- batched attention + output --------------------------------------
__global__ void __launch_bounds__(256) att_kernel(const float* __restrict__ enc,
                                                  const float* __restrict__ Wp,
                                                  const float* __restrict__ bp,
                                                  const int* __restrict__ lens,
                                                  float* __restrict__ out) {
    __shared__ float As[16][68];
    __shared__ float Bs[16][68];
    __shared__ float ec_s[64][2];
    const int bb = blockIdx.x >> 3;
    const int t0 = (blockIdx.x & 7) << 6;
    const int tid = threadIdx.x;
    const int ty = tid >> 4, tx = tid & 15;
    const int len = lens[bb];

    float ph0[4], ph1[4];
#pragma unroll
    for (int i = 0; i < 4; i++) {
        const int t = t0 + ty * 4 + i;
        const float* h = g_hist + ((size_t)bb * SS + t) * HH + tx * 64;
        float s0 = 0.f, s1 = 0.f;
#pragma unroll
        for (int c = 0; c < 16; c++) {
            float4 hv = *(const float4*)(h + c * 4);
            float4 w0 = *(const float4*)(Wp + 1024 + tx * 64 + c * 4);
            float4 w1 = *(const float4*)(Wp + 3072 + tx * 64 + c * 4);
            s0 += hv.x * w0.x + hv.y * w0.y + hv.z * w0.z + hv.w * w0.w;
            s1 += hv.x * w1.x + hv.y * w1.y + hv.z * w1.z + hv.w * w1.w;
        }
#pragma unroll
        for (int o = 8; o; o >>= 1) {
            s0 += __shfl_xor_sync(~0u, s0, o);
            s1 += __shfl_xor_sync(~0u, s1, o);
        }
        ph0[i] = s0; ph1[i] = s1;
    }

    float m[4], l[4], a0[4], a1[4];
#pragma unroll
    for (int i = 0; i < 4; i++) { m[i] = -1e30f; l[i] = 0.f; a0[i] = 0.f; a1[i] = 0.f; }

    const int am = tid >> 2, ak4 = (tid & 3) << 2;
    const float* hrow = g_hist + ((size_t)bb * SS + t0 + am) * HH + ak4;

    for (int sbase = 0; sbase < len; sbase += 64) {
        __syncthreads();
        if (tid < 64) {
            float2 e = *(const float2*)&g_ec[((size_t)bb * SS + sbase + tid) * 2];
            ec_s[tid][0] = e.x; ec_s[tid][1] = e.y;
        }
        const float* erow = enc + ((size_t)(sbase + am) * BB + bb) * HH + ak4;
        unsigned long long sc[4][2];
#pragma unroll
        for (int i = 0; i < 4; i++) { sc[i][0] = 0ull; sc[i][1] = 0ull; }

        for (int c = 0; c < 64; c++) {
            __syncthreads();
            float4 a4 = *(const float4*)(hrow + c * 16);
            As[ak4 + 0][am] = a4.x; As[ak4 + 1][am] = a4.y;
            As[ak4 + 2][am] = a4.z; As[ak4 + 3][am] = a4.w;
            float4 b4 = *(const float4*)(erow + c * 16);
            Bs[ak4 + 0][am] = b4.x; Bs[ak4 + 1][am] = b4.y;
            Bs[ak4 + 2][am] = b4.z; Bs[ak4 + 3][am] = b4.w;
            __syncthreads();
#pragma unroll
            for (int k = 0; k < 16; k++) {
                float4 av = *(const float4*)&As[k][ty * 4];
                ulonglong2 bpv = *(const ulonglong2*)&Bs[k][tx * 4];
                unsigned long long ax = pk2(av.x), ay = pk2(av.y);
                unsigned long long az = pk2(av.z), aw = pk2(av.w);
                fma2(sc[0][0], ax, bpv.x); fma2(sc[0][1], ax, bpv.y);
                fma2(sc[1][0], ay, bpv.x); fma2(sc[1][1], ay, bpv.y);
                fma2(sc[2][0], az, bpv.x); fma2(sc[2][1], az, bpv.y);
                fma2(sc[3][0], aw, bpv.x); fma2(sc[3][1], aw, bpv.y);
            }
        }

#pragma unroll
        for (int i = 0; i < 4; i++) {
            float s4[4];
            unp(sc[i][0], s4[0], s4[1]);
            unp(sc[i][1], s4[2], s4[3]);
#pragma unroll
            for (int j = 0; j < 4; j++)
                if (sbase + tx * 4 + j >= len) s4[j] = -1e30f;
            float cm = fmaxf(fmaxf(s4[0], s4[1]), fmaxf(s4[2], s4[3]));
#pragma unroll
            for (int o = 8; o; o >>= 1) cm = fmaxf(cm, __shfl_xor_sync(~0u, cm, o));
            const float mn = fmaxf(m[i], cm);
            const float alpha = __expf(m[i] - mn);
            float ws = 0.f, w0 = 0.f, w1 = 0.f;
#pragma unroll
            for (int j = 0; j < 4; j++) {
                float w = __expf(s4[j] - mn);
                ws += w;
                w0 += w * ec_s[tx * 4 + j][0];
                w1 += w * ec_s[tx * 4 + j][1];
            }
#pragma unroll
            for (int o = 8; o; o >>= 1) {
                ws += __shfl_xor_sync(~0u, ws, o);
                w0 += __shfl_xor_sync(~0u, w0, o);
                w1 += __shfl_xor_sync(~0u, w1, o);
            }
            l[i] = l[i] * alpha + ws;
            a0[i] = a0[i] * alpha + w0;
            a1[i] = a1[i] * alpha + w1;
            m[i] = mn;
        }
    }

    if (tx == 0) {
#pragma unroll
        for (int i = 0; i < 4; i++) {
            const int t = t0 + ty * 4 + i;
            const float inv = 1.f / l[i];
            out[((size_t)bb * SS + t) * 2 + 0] = a0[i] * inv + ph0[i] + bp[0];
            out[((size_t)bb * SS + t) * 2 + 1] = a1[i] * inv + ph1[i] + bp[1];
        }
    }
}

extern "C" void kernel_launch(void* const* d_in, const int* in_sizes, int n_in,
                              void* d_out, int out_size) {
    const float* enc  = (const float*)d_in[0];
    const float* last = (const float*)d_in[1];
    const float* Wih  = (const float*)d_in[2];
    const float* Whh  = (const float*)d_in[3];
    const float* bih  = (const float*)d_in[4];
    const float* bhh  = (const float*)d_in[5];
    const float* Wp   = (const float*)d_in[6];
    const float* bp   = (const float*)d_in[7];
    const int*   lens = (const int*)d_in[8];
    float* out = (float*)d_out;

    cudaFuncSetAttribute(rec_kernel, cudaFuncAttributeMaxDynamicSharedMemorySize, SM_TOTAL);
    prep_kernel<<<4096, 256>>>(Wih, Whh, bih, bhh, last);
    gemm0_kernel<<<dim3(64, 2), 128>>>();
    fuse0_kernel<<<BB, 256>>>();
    ec_kernel<<<256, 256>>>(enc, Wp);
    rec_kernel<<<NBLK, 256, SM_TOTAL>>>();
    att_kernel<<<1024, 256>>>(enc, Wp, bp, lens, out);
}